// round 13
// baseline (speedup 1.0000x reference)
#include <cuda_runtime.h>
#include <cuda_fp16.h>
#include <cstdint>
#include <cstddef>

#define THREADS 256
#define GRID    444
#define NTILES  8192          // 524288 rows / 64

#define S 144                 // A/B tile row stride (bytes), conflict-free
// smem byte offsets (per CTA, tile M=64)
#define AP0   0               // A0: 64 x 64 fp16 (h1 pos j)
#define AP1   9216            // A1: 64 x 64 fp16 (h1 pos 1+j)
#define A2    18432           // h2 parity-permuted: col = c2 + 32p
#define B1    27648           // W2 reshaped 32 x 64 (fp16) — init staging
#define B2HI  32256           // Wp column-permuted 64 x 64 (fp16 hi/lo) — init staging
#define B2LO  41472
#define CST   50688           // floats: W1[128], b1[32]
#define SO    288             // out staging row stride (bytes)
#define OUTS  51456           // out staging: 64 x 288B
#define SMEM_BYTES (51456 + 64 * 288)

static __device__ __forceinline__ uint32_t smem_u32(const void* p) {
    uint32_t a;
    asm("{ .reg .u64 t; cvta.to.shared.u64 t, %1; cvt.u32.u64 %0, t; }" : "=r"(a) : "l"(p));
    return a;
}
static __device__ __forceinline__ uint16_t h16(float v) {
    __half h = __float2half_rn(v);
    return reinterpret_cast<uint16_t&>(h);
}
static __device__ __forceinline__ uint32_t h2pack(float vlo, float vhi) {
    uint32_t r;
    asm("cvt.rn.f16x2.f32 %0, %1, %2;" : "=r"(r) : "f"(vhi), "f"(vlo));
    return r;
}
static __device__ __forceinline__ void hsplit(float v, uint16_t& h, uint16_t& l) {
    __half hh = __float2half_rn(v);
    float vh = __half2float(hh);
    __half hl = __float2half_rn(v - vh);
    h = reinterpret_cast<uint16_t&>(hh);
    l = reinterpret_cast<uint16_t&>(hl);
}

#define LDSM4(r, addr) \
    asm volatile("ldmatrix.sync.aligned.m8n8.x4.shared.b16 {%0,%1,%2,%3}, [%4];" \
        : "=r"((r)[0]), "=r"((r)[1]), "=r"((r)[2]), "=r"((r)[3]) : "r"(addr))

#define MMA(d, a, b0, b1) \
    asm volatile("mma.sync.aligned.m16n8k16.row.col.f32.f16.f16.f32 " \
        "{%0,%1,%2,%3}, {%4,%5,%6,%7}, {%8,%9}, {%0,%1,%2,%3};" \
        : "+f"((d)[0]), "+f"((d)[1]), "+f"((d)[2]), "+f"((d)[3]) \
        : "r"((a)[0]), "r"((a)[1]), "r"((a)[2]), "r"((a)[3]), "r"(b0), "r"(b1))

__global__ __launch_bounds__(THREADS, 3)
void cnn_encoder_mma9(const float* __restrict__ x,
                      const float* __restrict__ W1, const float* __restrict__ b1,
                      const float* __restrict__ W2, const float* __restrict__ b2,
                      const float* __restrict__ Wp, const float* __restrict__ bp,
                      float* __restrict__ out)
{
    extern __shared__ char smc[];
    const uint32_t sb = smem_u32(smc);
    float* cst = (float*)(smc + CST);   // W1[0:128) b1[128:160)

    const int t    = threadIdx.x;
    const int w    = t >> 5;
    const int lane = t & 31;
    const int g    = lane >> 2;
    const int tg   = lane & 3;
    // GEMM1 roles: parity group + 2m x 2n grid
    const int pg   = w >> 2;
    const int wm1  = w & 1;
    const int wn1  = (w >> 1) & 1;
    // GEMM2 roles: 2m x 4n grid
    const int wm2  = w & 1;
    const int wn2  = w >> 1;

    // ---- stage consts + B tiles (once) ----
    if (t < 128) cst[t] = W1[t];
    if (t < 32)  cst[128 + t] = b1[t];

    // B1 = W2 reshaped [c2=32][k=64], single fp16
    for (int i = t; i < 32 * 64; i += THREADS) {
        int c2 = i >> 6, kk = i & 63;
        *(uint16_t*)(smc + B1 + c2 * S + kk * 2) = h16(W2[i]);
    }
    // B2[o][kk] = Wp[o][2*(kk&31) + (kk>>5)]  (parity-permuted columns), fp16 hi/lo
    for (int i = t; i < 64 * 64; i += THREADS) {
        int o = i >> 6, kk = i & 63;
        uint16_t h, l; hsplit(Wp[o * 64 + 2 * (kk & 31) + (kk >> 5)], h, l);
        *(uint16_t*)(smc + B2HI + o * S + kk * 2) = h;
        *(uint16_t*)(smc + B2LO + o * S + kk * 2) = l;
    }

    // per-thread biases
    float b2a[2], b2c[2], bpv[2][2];
    #pragma unroll
    for (int nt = 0; nt < 2; nt++) {
        b2a[nt] = b2[16 * wn1 + 8 * nt + 2 * tg];
        b2c[nt] = b2[16 * wn1 + 8 * nt + 2 * tg + 1];
        bpv[nt][0] = bp[16 * wn2 + 8 * nt + 2 * tg];
        bpv[nt][1] = bp[16 * wn2 + 8 * nt + 2 * tg + 1];
    }

    // ldmatrix lane addressing (validated pattern)
    const int mat  = lane >> 3;
    const int lrow = (lane & 7) + 8 * (mat & 1);
    const int kby  = 16 * (mat >> 1);
    const uint32_t a1b = sb + (pg ? AP1 : AP0) + (32 * wm1 + lrow) * S + kby;
    const uint32_t b1b = sb + B1 + (16 * wn1 + lrow) * S + kby;
    const uint32_t a2b = sb + A2 + (32 * wm2 + lrow) * S + kby;
    const uint32_t b2b = sb + B2HI + (16 * wn2 + lrow) * S + kby;

    const int row = t & 63;       // conv: row within 64-row tile
    const int qh  = t >> 6;       // conv: 8-channel group 0..3

    __syncthreads();

    // ---- hoist ALL B fragments into persistent registers (tile-invariant) ----
    uint32_t b1f[4][4], b2fh[4][4], b2fl[4][4];
    #pragma unroll
    for (int kt = 0; kt < 4; kt++) {
        LDSM4(b1f[kt],  b1b + kt * 32);
        LDSM4(b2fh[kt], b2b + kt * 32);
        LDSM4(b2fl[kt], b2b + kt * 32 + (B2LO - B2HI));
    }

    for (int tile = blockIdx.x; tile < NTILES; tile += GRID) {
        // ================= conv1 -> A0/A1 (single fp16, packed cvt) =================
        {
            const float4* xr = (const float4*)(x + ((size_t)tile * 64 + row) * 8);
            float4 xa = xr[0], xb = xr[1];
            const float x0 = xa.x, x1 = xa.y, x2 = xa.z, x3 = xa.w;
            const float x4 = xb.x, x5 = xb.y, x6 = xb.z, x7 = xb.w;

            uint32_t a0[8], a1[8];
            #pragma unroll
            for (int u = 0; u < 8; u++) {
                int c1 = 8 * qh + u;
                float4 wv = ((const float4*)cst)[c1];
                float bb  = cst[128 + c1];
                float p0 = fmaxf(bb + wv.x * x0 + wv.y * x1 + wv.z * x4 + wv.w * x5, 0.f);
                float p1 = fmaxf(bb + wv.x * x1 + wv.y * x2 + wv.z * x5 + wv.w * x6, 0.f);
                float p2 = fmaxf(bb + wv.x * x2 + wv.y * x3 + wv.z * x6 + wv.w * x7, 0.f);
                a0[u] = h2pack(p0, p1);
                a1[u] = h2pack(p1, p2);
            }
            char* base = smc + row * S + 32 * qh;
            *(uint4*)(base + AP0)      = make_uint4(a0[0], a0[1], a0[2], a0[3]);
            *(uint4*)(base + AP0 + 16) = make_uint4(a0[4], a0[5], a0[6], a0[7]);
            *(uint4*)(base + AP1)      = make_uint4(a1[0], a1[1], a1[2], a1[3]);
            *(uint4*)(base + AP1 + 16) = make_uint4(a1[4], a1[5], a1[6], a1[7]);
        }
        __syncthreads();

        // ========= GEMM1 (parity pg): [64x32] = A_pg[64x64] * B1^T  (B in regs) =========
        float acc1[2][2][4];
        #pragma unroll
        for (int mt = 0; mt < 2; mt++)
            #pragma unroll
            for (int nt = 0; nt < 2; nt++)
                #pragma unroll
                for (int i = 0; i < 4; i++) acc1[mt][nt][i] = 0.f;

        #pragma unroll
        for (int kt = 0; kt < 4; kt++) {
            #pragma unroll
            for (int mt = 0; mt < 2; mt++) {
                uint32_t ah[4];
                LDSM4(ah, a1b + mt * (16 * S) + kt * 32);
                #pragma unroll
                for (int nt = 0; nt < 2; nt++)
                    MMA(acc1[mt][nt], ah, b1f[kt][nt], b1f[kt][nt + 2]);
            }
        }

        // ---- D1 epilogue: bias + relu -> A2 (single fp16, parity-permuted) ----
        #pragma unroll
        for (int mt = 0; mt < 2; mt++) {
            #pragma unroll
            for (int nt = 0; nt < 2; nt++) {
                int r0 = 32 * wm1 + 16 * mt + g;
                int cb = (32 * pg + 16 * wn1 + 8 * nt + 2 * tg) * 2;
                float f00 = fmaxf(acc1[mt][nt][0] + b2a[nt], 0.f);
                float f01 = fmaxf(acc1[mt][nt][1] + b2c[nt], 0.f);
                float f10 = fmaxf(acc1[mt][nt][2] + b2a[nt], 0.f);
                float f11 = fmaxf(acc1[mt][nt][3] + b2c[nt], 0.f);
                *(uint32_t*)(smc + A2 + r0 * S + cb)       = h2pack(f00, f01);
                *(uint32_t*)(smc + A2 + (r0 + 8) * S + cb) = h2pack(f10, f11);
            }
        }
        __syncthreads();

        // ========= GEMM2: [64x64] = A2[64x64] * B2^T  (B hi/lo in regs) =========
        float acc2[2][2][4];
        #pragma unroll
        for (int mt = 0; mt < 2; mt++)
            #pragma unroll
            for (int nt = 0; nt < 2; nt++)
                #pragma unroll
                for (int i = 0; i < 4; i++) acc2[mt][nt][i] = 0.f;

        #pragma unroll
        for (int kt = 0; kt < 4; kt++) {
            #pragma unroll
            for (int mt = 0; mt < 2; mt++) {
                uint32_t ah[4];
                LDSM4(ah, a2b + mt * (16 * S) + kt * 32);
                #pragma unroll
                for (int nt = 0; nt < 2; nt++) {
                    MMA(acc2[mt][nt], ah, b2fh[kt][nt], b2fh[kt][nt + 2]);
                    MMA(acc2[mt][nt], ah, b2fl[kt][nt], b2fl[kt][nt + 2]);
                }
            }
        }

        // ---- D2 epilogue: + bp -> smem staging (STS.64, cheap) ----
        #pragma unroll
        for (int mt = 0; mt < 2; mt++) {
            #pragma unroll
            for (int nt = 0; nt < 2; nt++) {
                int r0 = 32 * wm2 + 16 * mt + g;
                int cbo = (16 * wn2 + 8 * nt + 2 * tg) * 4;   // byte offset of float pair
                float2 v0 = make_float2(acc2[mt][nt][0] + bpv[nt][0], acc2[mt][nt][1] + bpv[nt][1]);
                float2 v1 = make_float2(acc2[mt][nt][2] + bpv[nt][0], acc2[mt][nt][3] + bpv[nt][1]);
                *(float2*)(smc + OUTS + r0 * SO + cbo)       = v0;
                *(float2*)(smc + OUTS + (r0 + 8) * SO + cbo) = v1;
            }
        }
        __syncthreads();

        // ---- coalesced copy: smem staging -> global (STG.128, full lines) ----
        {
            char* obase = (char*)out + (size_t)tile * 64 * 256;
            #pragma unroll
            for (int it = 0; it < 4; it++) {
                int cid = it * THREADS + t;       // 0..1023 chunks of 16B
                int r  = cid >> 4;
                int ch = cid & 15;
                uint4 v = *(uint4*)(smc + OUTS + r * SO + ch * 16);
                *(uint4*)(obase + r * 256 + ch * 16) = v;
            }
        }
        __syncthreads();   // protect A tiles + OUT staging before next tile
    }
}

extern "C" void kernel_launch(void* const* d_in, const int* in_sizes, int n_in,
                              void* d_out, int out_size)
{
    const float* x  = (const float*)d_in[0];
    const float* W1 = (const float*)d_in[1];
    const float* b1 = (const float*)d_in[2];
    const float* W2 = (const float*)d_in[3];
    const float* b2 = (const float*)d_in[4];
    const float* Wp = (const float*)d_in[5];
    const float* bp = (const float*)d_in[6];
    float* out = (float*)d_out;

    cudaFuncSetAttribute(cnn_encoder_mma9,
                         cudaFuncAttributeMaxDynamicSharedMemorySize, SMEM_BYTES);

    cnn_encoder_mma9<<<GRID, THREADS, SMEM_BYTES>>>(x, W1, b1, W2, b2, Wp, bp, out);
}

// round 14
// speedup vs baseline: 1.1279x; 1.1279x over previous
#include <cuda_runtime.h>
#include <cuda_fp16.h>
#include <cstdint>
#include <cstddef>

#define THREADS 128
#define GRID    888
#define NTILES  16384         // 524288 rows / 32

#define S 144                 // row stride (bytes), conflict-free
// smem byte offsets (per CTA, tile M=32)
#define AP0   0               // A0: 32 x 64 fp16 (h1 pos j)
#define AP1   4608            // A1: 32 x 64 fp16 (h1 pos 1+j)
#define A2    9216            // h2 parity-permuted: col = c2 + 32p (32 x 64)
#define B1    13824           // W2 reshaped 32 x 64 (fp16)
#define B2HI  18432           // Wp column-permuted 64 x 64 (fp16 hi/lo)
#define B2LO  27648
#define CST   36864           // floats: W1[128], b1[32]
#define SMEM_BYTES (36864 + 160 * 4)

static __device__ __forceinline__ uint32_t smem_u32(const void* p) {
    uint32_t a;
    asm("{ .reg .u64 t; cvta.to.shared.u64 t, %1; cvt.u32.u64 %0, t; }" : "=r"(a) : "l"(p));
    return a;
}
static __device__ __forceinline__ uint16_t h16(float v) {
    __half h = __float2half_rn(v);
    return reinterpret_cast<uint16_t&>(h);
}
static __device__ __forceinline__ uint32_t h2pack(float vlo, float vhi) {
    uint32_t r;
    asm("cvt.rn.f16x2.f32 %0, %1, %2;" : "=r"(r) : "f"(vhi), "f"(vlo));
    return r;
}
static __device__ __forceinline__ void hsplit(float v, uint16_t& h, uint16_t& l) {
    __half hh = __float2half_rn(v);
    float vh = __half2float(hh);
    __half hl = __float2half_rn(v - vh);
    h = reinterpret_cast<uint16_t&>(hh);
    l = reinterpret_cast<uint16_t&>(hl);
}

#define LDSM4(r, addr) \
    asm volatile("ldmatrix.sync.aligned.m8n8.x4.shared.b16 {%0,%1,%2,%3}, [%4];" \
        : "=r"((r)[0]), "=r"((r)[1]), "=r"((r)[2]), "=r"((r)[3]) : "r"(addr))

#define MMA(d, a, b0, b1) \
    asm volatile("mma.sync.aligned.m16n8k16.row.col.f32.f16.f16.f32 " \
        "{%0,%1,%2,%3}, {%4,%5,%6,%7}, {%8,%9}, {%0,%1,%2,%3};" \
        : "+f"((d)[0]), "+f"((d)[1]), "+f"((d)[2]), "+f"((d)[3]) \
        : "r"((a)[0]), "r"((a)[1]), "r"((a)[2]), "r"((a)[3]), "r"(b0), "r"(b1))

__global__ __launch_bounds__(THREADS, 6)
void cnn_encoder_mma10(const float* __restrict__ x,
                       const float* __restrict__ W1, const float* __restrict__ b1,
                       const float* __restrict__ W2, const float* __restrict__ b2,
                       const float* __restrict__ Wp, const float* __restrict__ bp,
                       float* __restrict__ out)
{
    extern __shared__ char smc[];
    const uint32_t sb = smem_u32(smc);
    float* cst = (float*)(smc + CST);   // W1[0:128) b1[128:160)

    const int t    = threadIdx.x;
    const int w    = t >> 5;      // 0..3
    const int lane = t & 31;
    const int g    = lane >> 2;
    const int tg   = lane & 3;
    // GEMM1 roles: parity group (w>>1) x n-half (w&1); all 32 rows per warp
    const int pg   = w >> 1;
    const int wn1  = w & 1;
    // GEMM2 roles: 1m x 4n grid; all 32 rows per warp
    const int wn2  = w;

    // ---- stage consts + B tiles (once) ----
    if (t < 128) cst[t] = W1[t];
    if (t < 32)  cst[128 + t] = b1[t];

    // B1 = W2 reshaped [c2=32][k=64], single fp16
    for (int i = t; i < 32 * 64; i += THREADS) {
        int c2 = i >> 6, kk = i & 63;
        *(uint16_t*)(smc + B1 + c2 * S + kk * 2) = h16(W2[i]);
    }
    // B2[o][kk] = Wp[o][2*(kk&31) + (kk>>5)]  (parity-permuted columns), fp16 hi/lo
    for (int i = t; i < 64 * 64; i += THREADS) {
        int o = i >> 6, kk = i & 63;
        uint16_t h, l; hsplit(Wp[o * 64 + 2 * (kk & 31) + (kk >> 5)], h, l);
        *(uint16_t*)(smc + B2HI + o * S + kk * 2) = h;
        *(uint16_t*)(smc + B2LO + o * S + kk * 2) = l;
    }

    // per-thread biases
    float b2a[2], b2c[2], bpv[2][2];
    #pragma unroll
    for (int nt = 0; nt < 2; nt++) {
        b2a[nt] = b2[16 * wn1 + 8 * nt + 2 * tg];
        b2c[nt] = b2[16 * wn1 + 8 * nt + 2 * tg + 1];
        bpv[nt][0] = bp[16 * wn2 + 8 * nt + 2 * tg];
        bpv[nt][1] = bp[16 * wn2 + 8 * nt + 2 * tg + 1];
    }

    // ldmatrix lane addressing (validated pattern)
    const int mat  = lane >> 3;
    const int lrow = (lane & 7) + 8 * (mat & 1);
    const int kby  = 16 * (mat >> 1);
    const uint32_t a1b = sb + (pg ? AP1 : AP0) + lrow * S + kby;
    const uint32_t b1b = sb + B1 + (16 * wn1 + lrow) * S + kby;
    const uint32_t a2b = sb + A2 + lrow * S + kby;
    const uint32_t b2b = sb + B2HI + (16 * wn2 + lrow) * S + kby;

    const int row = t & 31;       // conv: row within 32-row tile
    const int qh  = t >> 5;       // conv: 8-channel group 0..3

    __syncthreads();

    // ---- hoist B1 fragments into persistent registers (tile-invariant) ----
    uint32_t b1f[4][4];
    #pragma unroll
    for (int kt = 0; kt < 4; kt++)
        LDSM4(b1f[kt], b1b + kt * 32);

    for (int tile = blockIdx.x; tile < NTILES; tile += GRID) {
        // ================= conv1 -> A0/A1 (single fp16, packed cvt) =================
        {
            const float4* xr = (const float4*)(x + ((size_t)tile * 32 + row) * 8);
            float4 xa = xr[0], xb = xr[1];
            const float x0 = xa.x, x1 = xa.y, x2 = xa.z, x3 = xa.w;
            const float x4 = xb.x, x5 = xb.y, x6 = xb.z, x7 = xb.w;

            uint32_t a0[8], a1[8];
            #pragma unroll
            for (int u = 0; u < 8; u++) {
                int c1 = 8 * qh + u;
                float4 wv = ((const float4*)cst)[c1];
                float bb  = cst[128 + c1];
                float p0 = fmaxf(bb + wv.x * x0 + wv.y * x1 + wv.z * x4 + wv.w * x5, 0.f);
                float p1 = fmaxf(bb + wv.x * x1 + wv.y * x2 + wv.z * x5 + wv.w * x6, 0.f);
                float p2 = fmaxf(bb + wv.x * x2 + wv.y * x3 + wv.z * x6 + wv.w * x7, 0.f);
                a0[u] = h2pack(p0, p1);
                a1[u] = h2pack(p1, p2);
            }
            char* base = smc + row * S + 32 * qh;
            *(uint4*)(base + AP0)      = make_uint4(a0[0], a0[1], a0[2], a0[3]);
            *(uint4*)(base + AP0 + 16) = make_uint4(a0[4], a0[5], a0[6], a0[7]);
            *(uint4*)(base + AP1)      = make_uint4(a1[0], a1[1], a1[2], a1[3]);
            *(uint4*)(base + AP1 + 16) = make_uint4(a1[4], a1[5], a1[6], a1[7]);
        }
        __syncthreads();

        // ========= GEMM1 (parity pg): [32x32] = A_pg[32x64] * B1^T  (B in regs) =========
        float acc1[2][2][4];
        #pragma unroll
        for (int mt = 0; mt < 2; mt++)
            #pragma unroll
            for (int nt = 0; nt < 2; nt++)
                #pragma unroll
                for (int i = 0; i < 4; i++) acc1[mt][nt][i] = 0.f;

        #pragma unroll
        for (int kt = 0; kt < 4; kt++) {
            #pragma unroll
            for (int mt = 0; mt < 2; mt++) {
                uint32_t ah[4];
                LDSM4(ah, a1b + mt * (16 * S) + kt * 32);
                #pragma unroll
                for (int nt = 0; nt < 2; nt++)
                    MMA(acc1[mt][nt], ah, b1f[kt][nt], b1f[kt][nt + 2]);
            }
        }

        // ---- D1 epilogue: bias + relu -> A2 (single fp16, parity-permuted) ----
        #pragma unroll
        for (int mt = 0; mt < 2; mt++) {
            #pragma unroll
            for (int nt = 0; nt < 2; nt++) {
                int r0 = 16 * mt + g;
                int cb = (32 * pg + 16 * wn1 + 8 * nt + 2 * tg) * 2;
                float f00 = fmaxf(acc1[mt][nt][0] + b2a[nt], 0.f);
                float f01 = fmaxf(acc1[mt][nt][1] + b2c[nt], 0.f);
                float f10 = fmaxf(acc1[mt][nt][2] + b2a[nt], 0.f);
                float f11 = fmaxf(acc1[mt][nt][3] + b2c[nt], 0.f);
                *(uint32_t*)(smc + A2 + r0 * S + cb)       = h2pack(f00, f01);
                *(uint32_t*)(smc + A2 + (r0 + 8) * S + cb) = h2pack(f10, f11);
            }
        }
        __syncthreads();

        // ========= GEMM2: [32x64] = A2[32x64] * B2^T  (B hi/lo from smem) =========
        float acc2[2][2][4];
        #pragma unroll
        for (int mt = 0; mt < 2; mt++)
            #pragma unroll
            for (int nt = 0; nt < 2; nt++)
                #pragma unroll
                for (int i = 0; i < 4; i++) acc2[mt][nt][i] = 0.f;

        #pragma unroll
        for (int kt = 0; kt < 4; kt++) {
            uint32_t bh[4], bl[4];
            LDSM4(bh, b2b + kt * 32);
            LDSM4(bl, b2b + kt * 32 + (B2LO - B2HI));
            #pragma unroll
            for (int mt = 0; mt < 2; mt++) {
                uint32_t ah[4];
                LDSM4(ah, a2b + mt * (16 * S) + kt * 32);
                #pragma unroll
                for (int nt = 0; nt < 2; nt++) {
                    MMA(acc2[mt][nt], ah, bh[nt], bh[nt + 2]);
                    MMA(acc2[mt][nt], ah, bl[nt], bl[nt + 2]);
                }
            }
        }

        // ---- D2 epilogue: + bp -> out ----
        #pragma unroll
        for (int mt = 0; mt < 2; mt++) {
            #pragma unroll
            for (int nt = 0; nt < 2; nt++) {
                size_t r0 = (size_t)tile * 32 + 16 * mt + g;
                int ncol = 16 * wn2 + 8 * nt + 2 * tg;
                float2 v0 = make_float2(acc2[mt][nt][0] + bpv[nt][0], acc2[mt][nt][1] + bpv[nt][1]);
                float2 v1 = make_float2(acc2[mt][nt][2] + bpv[nt][0], acc2[mt][nt][3] + bpv[nt][1]);
                *(float2*)(out + r0 * 64 + ncol)       = v0;
                *(float2*)(out + (r0 + 8) * 64 + ncol) = v1;
            }
        }
        __syncthreads();   // protect A tiles before next tile's writes
    }
}

extern "C" void kernel_launch(void* const* d_in, const int* in_sizes, int n_in,
                              void* d_out, int out_size)
{
    const float* x  = (const float*)d_in[0];
    const float* W1 = (const float*)d_in[1];
    const float* b1 = (const float*)d_in[2];
    const float* W2 = (const float*)d_in[3];
    const float* b2 = (const float*)d_in[4];
    const float* Wp = (const float*)d_in[5];
    const float* bp = (const float*)d_in[6];
    float* out = (float*)d_out;

    cudaFuncSetAttribute(cnn_encoder_mma10,
                         cudaFuncAttributeMaxDynamicSharedMemorySize, SMEM_BYTES);

    cnn_encoder_mma10<<<GRID, THREADS, SMEM_BYTES>>>(x, W1, b1, W2, b2, Wp, bp, out);
}